// round 6
// baseline (speedup 1.0000x reference)
#include <cuda_runtime.h>
#include <cstdint>

#define BATCH 4
#define SEQ   2048
#define EMB   1024
#define NH    16
#define HD    64
#define MROWS (BATCH*SEQ)
#define KDIM  EMB

// Scratch: Q,K row-major [B,H,T,hd]; V d-major [B,H,hd,T]
__device__ float g_q[BATCH*NH*SEQ*HD];
__device__ float g_k[BATCH*NH*SEQ*HD];
__device__ float g_v[BATCH*NH*HD*SEQ];

__device__ __forceinline__ unsigned tf32_of(float v) {
    unsigned r; asm("cvt.rna.tf32.f32 %0, %1;" : "=r"(r) : "f"(v)); return r;
}

__device__ __forceinline__ void mma8(float* d, const unsigned* a, unsigned b0, unsigned b1) {
    asm volatile(
        "mma.sync.aligned.m16n8k8.row.col.f32.tf32.tf32.f32 "
        "{%0,%1,%2,%3}, {%4,%5,%6,%7}, {%8,%9}, {%0,%1,%2,%3};"
        : "+f"(d[0]), "+f"(d[1]), "+f"(d[2]), "+f"(d[3])
        : "r"(a[0]), "r"(a[1]), "r"(a[2]), "r"(a[3]), "r"(b0), "r"(b1));
}

__device__ __forceinline__ uint4 ldmx4(unsigned addr) {
    uint4 r;
    asm volatile("ldmatrix.sync.aligned.m8n8.x4.shared.b16 {%0,%1,%2,%3}, [%4];"
        : "=r"(r.x), "=r"(r.y), "=r"(r.z), "=r"(r.w) : "r"(addr));
    return r;
}

__device__ __forceinline__ uint32_t smem_u32(const void* p) {
    uint32_t a;
    asm("{ .reg .u64 t; cvta.to.shared.u64 t, %1; cvt.u32.u64 %0, t; }" : "=r"(a) : "l"(p));
    return a;
}

// ---------------------------------------------------------------------------
// Kernel 1: qkv = x @ W^T + b.  4 warps, each a 64x64 quadrant of 128x128.
// ---------------------------------------------------------------------------
#define GBM 128
#define GBN 128
#define GBK 32
#define GPAD 36
#define GEMM_SMEM (2*(GBM + GBN)*GPAD*4)

__global__ void __launch_bounds__(128, 2)
qkv_gemm_mma(const float* __restrict__ x, const float* __restrict__ W,
             const float* __restrict__ bias) {
    extern __shared__ unsigned gsm[];
    unsigned* As = gsm;                       // [2][GBM*GPAD]
    unsigned* Bs = gsm + 2*GBM*GPAD;          // [2][GBN*GPAD]

    const int tid  = threadIdx.x;
    const int lane = tid & 31;
    const int warp = tid >> 5;                // 0..3
    const int g    = lane >> 2;
    const int t4   = lane & 3;
    const int wm   = warp >> 1;               // 0..1 (m half)
    const int wn   = warp & 1;                // 0..1 (n half)
    const int m0   = blockIdx.y * GBM;
    const int n0   = blockIdx.x * GBN;

    const float* xp = x + (size_t)m0 * KDIM;
    const float* wp = W + (size_t)n0 * KDIM;

    // ldmatrix per-thread offsets
    const int arow = ((lane >> 3) & 1)*8 + (lane & 7);
    const int acol = (lane >> 4) * 4;
    const int brow = (lane >> 4)*8 + (lane & 7);
    const int bcol = ((lane >> 3) & 1) * 4;
    const unsigned aBase = smem_u32(As) + ((wm*64 + arow)*GPAD + acol)*4;
    const unsigned bBase = smem_u32(Bs) + ((wn*64 + brow)*GPAD + bcol)*4;

    float acc[4][8][4];
    #pragma unroll
    for (int mt = 0; mt < 4; mt++)
        #pragma unroll
        for (int nt = 0; nt < 8; nt++)
            #pragma unroll
            for (int r = 0; r < 4; r++) acc[mt][nt][r] = 0.f;

    float4 fa[8], fb[8];

    // prologue: stage kt=0
    #pragma unroll
    for (int p = 0; p < 8; p++) {
        const int id = tid + p*128;
        const int r  = id >> 3;
        const int c  = (id & 7) * 4;
        fa[p] = *(const float4*)(xp + (size_t)r*KDIM + c);
        fb[p] = *(const float4*)(wp + (size_t)r*KDIM + c);
    }
    #pragma unroll
    for (int p = 0; p < 8; p++) {
        const int id = tid + p*128;
        const int r  = id >> 3;
        const int c  = (id & 7) * 4;
        *(uint4*)&As[r*GPAD + c] = make_uint4(tf32_of(fa[p].x), tf32_of(fa[p].y), tf32_of(fa[p].z), tf32_of(fa[p].w));
        *(uint4*)&Bs[r*GPAD + c] = make_uint4(tf32_of(fb[p].x), tf32_of(fb[p].y), tf32_of(fb[p].z), tf32_of(fb[p].w));
    }
    __syncthreads();

    const int NK = KDIM / GBK;                // 32
    for (int kt = 0; kt < NK; kt++) {
        if (kt + 1 < NK) {
            const int ko = (kt + 1) * GBK;
            #pragma unroll
            for (int p = 0; p < 8; p++) {
                const int id = tid + p*128;
                const int r  = id >> 3;
                const int c  = (id & 7) * 4;
                fa[p] = *(const float4*)(xp + (size_t)r*KDIM + ko + c);
                fb[p] = *(const float4*)(wp + (size_t)r*KDIM + ko + c);
            }
        }
        {
            const unsigned abuf = aBase + (kt & 1)*GBM*GPAD*4;
            const unsigned bbuf = bBase + (kt & 1)*GBN*GPAD*4;
            #pragma unroll
            for (int ks = 0; ks < 4; ks++) {
                const int k0 = ks * 8;
                uint4 af[4], bf[4];
                #pragma unroll
                for (int mt = 0; mt < 4; mt++) af[mt] = ldmx4(abuf + (mt*16*GPAD + k0)*4);
                #pragma unroll
                for (int j = 0; j < 4; j++)  bf[j]  = ldmx4(bbuf + (j*16*GPAD + k0)*4);
                #pragma unroll
                for (int mt = 0; mt < 4; mt++)
                    #pragma unroll
                    for (int j = 0; j < 4; j++) {
                        mma8(acc[mt][2*j],   &af[mt].x, bf[j].x, bf[j].y);
                        mma8(acc[mt][2*j+1], &af[mt].x, bf[j].z, bf[j].w);
                    }
            }
        }
        if (kt + 1 < NK) {
            unsigned* Ab = As + ((kt + 1) & 1)*GBM*GPAD;
            unsigned* Bb = Bs + ((kt + 1) & 1)*GBN*GPAD;
            #pragma unroll
            for (int p = 0; p < 8; p++) {
                const int id = tid + p*128;
                const int r  = id >> 3;
                const int c  = (id & 7) * 4;
                *(uint4*)&Ab[r*GPAD + c] = make_uint4(tf32_of(fa[p].x), tf32_of(fa[p].y), tf32_of(fa[p].z), tf32_of(fa[p].w));
                *(uint4*)&Bb[r*GPAD + c] = make_uint4(tf32_of(fb[p].x), tf32_of(fb[p].y), tf32_of(fb[p].z), tf32_of(fb[p].w));
            }
            __syncthreads();
        }
    }

    // Epilogue: bias + scatter (Q,K row-major; V d-major)
    const int which = n0 / EMB;               // 0=q 1=k 2=v
    const int b     = m0 / SEQ;
    #pragma unroll
    for (int nt = 0; nt < 8; nt++) {
        const int col = n0 + wn*64 + nt*8 + 2*t4;
        const float b0v = bias[col];
        const float b1v = bias[col + 1];
        const int c = col % EMB;
        const int h = c >> 6;
        const int d = c & 63;
        #pragma unroll
        for (int mt = 0; mt < 4; mt++) {
            #pragma unroll
            for (int rr = 0; rr < 2; rr++) {
                const int m = m0 + wm*64 + mt*16 + g + rr*8;
                const int t = m % SEQ;
                const float v0 = acc[mt][nt][rr*2 + 0] + b0v;
                const float v1 = acc[mt][nt][rr*2 + 1] + b1v;
                if (which == 2) {
                    float* base = g_v + ((size_t)(b*NH + h)*HD + d)*SEQ + t;
                    base[0]   = v0;
                    base[SEQ] = v1;          // next d, same t
                } else {
                    float* qk = (which == 0 ? g_q : g_k);
                    *(float2*)&qk[((size_t)(b*NH + h)*SEQ + t)*HD + d] = make_float2(v0, v1);
                }
            }
        }
    }
}

// ---------------------------------------------------------------------------
// Kernel 2: causal flash attention. 4 warps, each M=32 of BQ=128; BKT=64.
// ---------------------------------------------------------------------------
#define KP 68
#define ATT_SMEM ((128*KP + 64*KP + 64*KP + 128*KP)*4)   // Qs,Ks,Vs,Ps

__global__ void __launch_bounds__(128, 2)
attn_mma(float* __restrict__ out) {
    extern __shared__ unsigned asm_[];
    unsigned* Qs = asm_;                      // [128 q][KP d]
    unsigned* Ks = Qs + 128*KP;               // [64 key][KP d]
    unsigned* Vs = Ks + 64*KP;                // [64 d][KP key]
    unsigned* Ps = Vs + 64*KP;                // [128 q][KP key]

    const int tid  = threadIdx.x;
    const int lane = tid & 31;
    const int w    = tid >> 5;                // 0..3, rows [w*32, w*32+32)
    const int g    = lane >> 2;
    const int t4   = lane & 3;
    const int qi   = gridDim.x - 1 - blockIdx.x;   // heavy tiles first
    const int q0   = qi * 128;
    const int bh   = blockIdx.y;

    const float* Qg = g_q + ((size_t)bh*SEQ + q0)*HD;
    const float* Kg = g_k + (size_t)bh*SEQ*HD;
    const float* Vg = g_v + (size_t)bh*HD*SEQ;

    const int arow = ((lane >> 3) & 1)*8 + (lane & 7);
    const int acol = (lane >> 4) * 4;
    const int brow = lane & 7;
    const int bcol = (lane >> 3) * 4;
    const unsigned qBase = smem_u32(Qs) + ((w*32 + arow)*KP + acol)*4;
    const unsigned pBase = smem_u32(Ps) + ((w*32 + arow)*KP + acol)*4;
    const unsigned kBase = smem_u32(Ks) + (brow*KP + bcol)*4;
    const unsigned vBase = smem_u32(Vs) + (brow*KP + bcol)*4;

    // Stage Q (pre-scaled by 1/8)
    #pragma unroll
    for (int p = 0; p < 16; p++) {
        const int id = tid + p*128;
        const int r  = id >> 4;
        const int c  = (id & 15) * 4;
        float4 v = *(const float4*)(Qg + (size_t)r*HD + c);
        *(uint4*)&Qs[r*KP + c] = make_uint4(
            tf32_of(v.x*0.125f), tf32_of(v.y*0.125f),
            tf32_of(v.z*0.125f), tf32_of(v.w*0.125f));
    }

    float o[2][8][4];
    #pragma unroll
    for (int mt = 0; mt < 2; mt++)
        #pragma unroll
        for (int nt = 0; nt < 8; nt++)
            #pragma unroll
            for (int r = 0; r < 4; r++) o[mt][nt][r] = 0.f;
    float m_run[4], l_run[4];
    #pragma unroll
    for (int a = 0; a < 4; a++) { m_run[a] = -1e30f; l_run[a] = 0.f; }

    const int row0 = q0 + w*32 + g;           // thread's first row; others +8,+16,+24
    const int nkt  = 2*qi + 2;

    for (int kt = 0; kt < nkt; kt++) {
        const int k0 = kt * 64;
        __syncthreads();   // prev tile readers done (covers Q staging on kt=0)
        #pragma unroll
        for (int p = 0; p < 8; p++) {
            const int id = tid + p*128;
            const int r  = id >> 4;
            const int c  = (id & 15) * 4;
            float4 kv = *(const float4*)(Kg + (size_t)(k0 + r)*HD + c);
            *(uint4*)&Ks[r*KP + c] = make_uint4(tf32_of(kv.x), tf32_of(kv.y), tf32_of(kv.z), tf32_of(kv.w));
            float4 vv = *(const float4*)(Vg + (size_t)r*SEQ + k0 + c);
            *(uint4*)&Vs[r*KP + c] = make_uint4(tf32_of(vv.x), tf32_of(vv.y), tf32_of(vv.z), tf32_of(vv.w));
        }
        __syncthreads();

        if (k0 > q0 + w*32 + 31) continue;    // warp fully above diagonal

        // ---- S = Q K^T ----
        float s[2][8][4];
        #pragma unroll
        for (int mt = 0; mt < 2; mt++)
            #pragma unroll
            for (int nt = 0; nt < 8; nt++)
                #pragma unroll
                for (int r = 0; r < 4; r++) s[mt][nt][r] = 0.f;
        #pragma unroll
        for (int kkp = 0; kkp < 4; kkp++) {
            uint4 qa00 = ldmx4(qBase + (kkp*16)*4);
            uint4 qa01 = ldmx4(qBase + (kkp*16 + 8)*4);
            uint4 qa10 = ldmx4(qBase + (16*KP + kkp*16)*4);
            uint4 qa11 = ldmx4(qBase + (16*KP + kkp*16 + 8)*4);
            #pragma unroll
            for (int nt = 0; nt < 8; nt++) {
                uint4 kb = ldmx4(kBase + (nt*8*KP + kkp*16)*4);
                mma8(s[0][nt], &qa00.x, kb.x, kb.y);
                mma8(s[0][nt], &qa01.x, kb.z, kb.w);
                mma8(s[1][nt], &qa10.x, kb.x, kb.y);
                mma8(s[1][nt], &qa11.x, kb.z, kb.w);
            }
        }

        // ---- causal mask (needed iff tile end exceeds warp's first row) ----
        if (k0 + 63 > q0 + w*32) {
            #pragma unroll
            for (int nt = 0; nt < 8; nt++) {
                const int col = k0 + nt*8 + 2*t4;
                #pragma unroll
                for (int mt = 0; mt < 2; mt++) {
                    const int r = row0 + mt*16;
                    if (col     > r    ) s[mt][nt][0] = -1e30f;
                    if (col + 1 > r    ) s[mt][nt][1] = -1e30f;
                    if (col     > r + 8) s[mt][nt][2] = -1e30f;
                    if (col + 1 > r + 8) s[mt][nt][3] = -1e30f;
                }
            }
        }

        // ---- online softmax: 4 rows/thread (row0 + 8a) ----
        float mx[4] = {-1e30f, -1e30f, -1e30f, -1e30f};
        #pragma unroll
        for (int nt = 0; nt < 8; nt++) {
            mx[0] = fmaxf(mx[0], fmaxf(s[0][nt][0], s[0][nt][1]));
            mx[1] = fmaxf(mx[1], fmaxf(s[0][nt][2], s[0][nt][3]));
            mx[2] = fmaxf(mx[2], fmaxf(s[1][nt][0], s[1][nt][1]));
            mx[3] = fmaxf(mx[3], fmaxf(s[1][nt][2], s[1][nt][3]));
        }
        float corr[4];
        #pragma unroll
        for (int a = 0; a < 4; a++) {
            mx[a] = fmaxf(mx[a], __shfl_xor_sync(0xffffffffu, mx[a], 1));
            mx[a] = fmaxf(mx[a], __shfl_xor_sync(0xffffffffu, mx[a], 2));
            const float mn = fmaxf(m_run[a], mx[a]);
            corr[a] = __expf(m_run[a] - mn);
            m_run[a] = mn;
        }

        float sum[4] = {0.f, 0.f, 0.f, 0.f};
        #pragma unroll
        for (int nt = 0; nt < 8; nt++) {
            const int pc = nt*8 + 2*t4;
            #pragma unroll
            for (int mt = 0; mt < 2; mt++) {
                const float p00 = __expf(s[mt][nt][0] - m_run[2*mt]);
                const float p01 = __expf(s[mt][nt][1] - m_run[2*mt]);
                const float p10 = __expf(s[mt][nt][2] - m_run[2*mt+1]);
                const float p11 = __expf(s[mt][nt][3] - m_run[2*mt+1]);
                sum[2*mt]   += p00 + p01;
                sum[2*mt+1] += p10 + p11;
                *(uint2*)&Ps[(w*32 + mt*16 + g    )*KP + pc] = make_uint2(tf32_of(p00), tf32_of(p01));
                *(uint2*)&Ps[(w*32 + mt*16 + g + 8)*KP + pc] = make_uint2(tf32_of(p10), tf32_of(p11));
            }
        }
        #pragma unroll
        for (int a = 0; a < 4; a++) {
            sum[a] += __shfl_xor_sync(0xffffffffu, sum[a], 1);
            sum[a] += __shfl_xor_sync(0xffffffffu, sum[a], 2);
            l_run[a] = l_run[a]*corr[a] + sum[a];
        }
        #pragma unroll
        for (int nt = 0; nt < 8; nt++) {
            o[0][nt][0] *= corr[0]; o[0][nt][1] *= corr[0];
            o[0][nt][2] *= corr[1]; o[0][nt][3] *= corr[1];
            o[1][nt][0] *= corr[2]; o[1][nt][1] *= corr[2];
            o[1][nt][2] *= corr[3]; o[1][nt][3] *= corr[3];
        }
        __syncwarp();   // P writes visible to warp's ldmatrix

        // ---- O += P V ----
        #pragma unroll
        for (int kkp = 0; kkp < 4; kkp++) {
            uint4 pa00 = ldmx4(pBase + (kkp*16)*4);
            uint4 pa01 = ldmx4(pBase + (kkp*16 + 8)*4);
            uint4 pa10 = ldmx4(pBase + (16*KP + kkp*16)*4);
            uint4 pa11 = ldmx4(pBase + (16*KP + kkp*16 + 8)*4);
            #pragma unroll
            for (int nt = 0; nt < 8; nt++) {
                uint4 vb = ldmx4(vBase + (nt*8*KP + kkp*16)*4);
                mma8(o[0][nt], &pa00.x, vb.x, vb.y);
                mma8(o[0][nt], &pa01.x, vb.z, vb.w);
                mma8(o[1][nt], &pa10.x, vb.x, vb.y);
                mma8(o[1][nt], &pa11.x, vb.z, vb.w);
            }
        }
        __syncwarp();   // P reads done before next tile's writes
    }

    // ---- epilogue: out[b, t, h*64 + d] ----
    const int bb = bh >> 4;
    const int h  = bh & 15;
    float inv[4];
    #pragma unroll
    for (int a = 0; a < 4; a++) inv[a] = 1.f / l_run[a];
    #pragma unroll
    for (int a = 0; a < 4; a++) {
        float* op = out + ((size_t)bb*SEQ + row0 + a*8)*EMB + h*HD;
        const int mt = a >> 1;
        const int rr = a & 1;
        #pragma unroll
        for (int nt = 0; nt < 8; nt++) {
            const int d = nt*8 + 2*t4;
            *(float2*)(op + d) = make_float2(o[mt][nt][rr*2]*inv[a], o[mt][nt][rr*2+1]*inv[a]);
        }
    }
}

// ---------------------------------------------------------------------------
extern "C" void kernel_launch(void* const* d_in, const int* in_sizes, int n_in,
                              void* d_out, int out_size) {
    const float* x    = (const float*)d_in[0];
    const float* W    = (const float*)d_in[1];
    const float* bias = (const float*)d_in[2];
    float* out = (float*)d_out;

    cudaFuncSetAttribute(qkv_gemm_mma, cudaFuncAttributeMaxDynamicSharedMemorySize, GEMM_SMEM);
    cudaFuncSetAttribute(attn_mma,     cudaFuncAttributeMaxDynamicSharedMemorySize, ATT_SMEM);

    dim3 g1(3*EMB/GBN, MROWS/GBM);            // (24, 64)
    qkv_gemm_mma<<<g1, 128, GEMM_SMEM>>>(x, W, bias);

    dim3 g2(SEQ/128, BATCH*NH);               // (16, 64)
    attn_mma<<<g2, 128, ATT_SMEM>>>(out);
}